// round 9
// baseline (speedup 1.0000x reference)
#include <cuda_runtime.h>
#include <cuda_fp16.h>
#include <mma.h>
#include <cstdint>

using namespace nvcuda;

#define N_NODES 50000
#define N_PAD   50048   // 782 * 64
#define N_EDGES 1600000
#define IN_DIM  256
#define OUT_DIM 128
#define T_STEPS 8

// Scratch (device globals — no allocation allowed)
__device__ __align__(16) __half g_x2[N_PAD * IN_DIM];    // x in fp16 (padded)
__device__ __align__(16) __half g_h2[N_PAD * OUT_DIM];   // h = x @ W (fp16)
__device__ float g_dinv[N_NODES];
__device__ __align__(16) int g_cnt[N_NODES];
__device__ int   g_off[N_NODES + 1];
__device__ int   g_cursor[N_NODES];
__device__ int   g_srcs[N_EDGES];

// ---------------------------------------------------------------------------
__global__ void k_zero_cnt() {
    int i = blockIdx.x * blockDim.x + threadIdx.x;
    if (i < N_NODES / 4) ((int4*)g_cnt)[i] = make_int4(0, 0, 0, 0);
    // N_NODES = 50000 divisible by 4
}

// 8 edges per thread: 2x int4 loads from the dst row (MLP + fewer threads)
__global__ __launch_bounds__(256) void k_hist(const int* __restrict__ ei) {
    int t = blockIdx.x * blockDim.x + threadIdx.x;
    if (t >= N_EDGES / 8) return;
    const int4* dp = (const int4*)(ei + N_EDGES);
    int4 a = dp[t * 2 + 0];
    int4 b = dp[t * 2 + 1];
    atomicAdd(&g_cnt[a.x], 1); atomicAdd(&g_cnt[a.y], 1);
    atomicAdd(&g_cnt[a.z], 1); atomicAdd(&g_cnt[a.w], 1);
    atomicAdd(&g_cnt[b.x], 1); atomicAdd(&g_cnt[b.y], 1);
    atomicAdd(&g_cnt[b.z], 1); atomicAdd(&g_cnt[b.w], 1);
}

// ---------------------------------------------------------------------------
__global__ __launch_bounds__(1024) void k_offsets() {
    const int TPB = 1024;
    const int PER = (N_NODES + TPB - 1) / TPB;
    __shared__ int warp_sums[32];

    int t = threadIdx.x;
    int lane = t & 31, wid = t >> 5;
    int base = t * PER;

    int total = 0;
    for (int i = 0; i < PER; i++) {
        int n = base + i;
        if (n < N_NODES) total += g_cnt[n];
    }

    int v = total;
#pragma unroll
    for (int off = 1; off < 32; off <<= 1) {
        int u = __shfl_up_sync(0xffffffff, v, off);
        if (lane >= off) v += u;
    }
    if (lane == 31) warp_sums[wid] = v;
    __syncthreads();
    if (wid == 0) {
        int w = warp_sums[lane];
#pragma unroll
        for (int off = 1; off < 32; off <<= 1) {
            int u = __shfl_up_sync(0xffffffff, w, off);
            if (lane >= off) w += u;
        }
        warp_sums[lane] = w;
    }
    __syncthreads();
    int excl = v - total + (wid > 0 ? warp_sums[wid - 1] : 0);

    int run = excl;
    for (int i = 0; i < PER; i++) {
        int n = base + i;
        if (n < N_NODES) {
            g_off[n] = run;
            g_cursor[n] = run;
            int c = g_cnt[n];
            run += c;
            g_dinv[n] = rsqrtf((float)(c + 1));
        }
    }
    if (t == TPB - 1) g_off[N_NODES] = run;
}

// 4 edges per thread: int4 src + int4 dst
__global__ __launch_bounds__(256) void k_csr(const int* __restrict__ ei) {
    int t = blockIdx.x * blockDim.x + threadIdx.x;
    if (t >= N_EDGES / 4) return;
    int4 s = ((const int4*)ei)[t];
    int4 d = ((const int4*)(ei + N_EDGES))[t];
    g_srcs[atomicAdd(&g_cursor[d.x], 1)] = s.x;
    g_srcs[atomicAdd(&g_cursor[d.y], 1)] = s.y;
    g_srcs[atomicAdd(&g_cursor[d.z], 1)] = s.z;
    g_srcs[atomicAdd(&g_cursor[d.w], 1)] = s.w;
}

// ---------------------------------------------------------------------------
// x fp32 -> fp16 (padded rows zero-filled)
// ---------------------------------------------------------------------------
__global__ __launch_bounds__(256) void k_cvt_x(const float* __restrict__ x) {
    const int TOT = N_PAD * IN_DIM / 4;
    int i = blockIdx.x * blockDim.x + threadIdx.x;
    if (i >= TOT) return;
    int row = i / (IN_DIM / 4);
    uint2 pk;
    if (row < N_NODES) {
        float4 v = ((const float4*)x)[i];
        __half2 h0 = __floats2half2_rn(v.x, v.y);
        __half2 h1 = __floats2half2_rn(v.z, v.w);
        pk.x = *(uint32_t*)&h0;
        pk.y = *(uint32_t*)&h1;
    } else {
        pk = make_uint2(0u, 0u);
    }
    ((uint2*)g_x2)[i] = pk;
}

// ---------------------------------------------------------------------------
// HMMA GEMM: h = x @ W via wmma 16x16x16 fp16 x fp16 + fp32 acc.
// ---------------------------------------------------------------------------
__global__ __launch_bounds__(128) void k_gemm_hmma(const float* __restrict__ W) {
    __shared__ __half Ws[128][128];   // 32 KB; aliased as fp32 staging on exit

    const int warp = threadIdx.x >> 5;
    const int row0 = blockIdx.x * 64 + warp * 16;

    wmma::fragment<wmma::accumulator, 16, 16, 16, float> accf[8];
#pragma unroll
    for (int nf = 0; nf < 8; nf++) wmma::fill_fragment(accf[nf], 0.0f);

#pragma unroll
    for (int phase = 0; phase < 2; phase++) {
        for (int idx = threadIdx.x; idx < 128 * 128 / 4; idx += 128) {
            int r = idx / 32;
            int c4 = idx % 32;
            float4 v = *(const float4*)&W[(size_t)(phase * 128 + r) * OUT_DIM + c4 * 4];
            __half2 h0 = __floats2half2_rn(v.x, v.y);
            __half2 h1 = __floats2half2_rn(v.z, v.w);
            uint2 pk;
            pk.x = *(uint32_t*)&h0;
            pk.y = *(uint32_t*)&h1;
            *(uint2*)&Ws[r][c4 * 4] = pk;
        }
        __syncthreads();

#pragma unroll
        for (int ks = 0; ks < 8; ks++) {
            wmma::fragment<wmma::matrix_a, 16, 16, 16, __half, wmma::row_major> a;
            wmma::load_matrix_sync(a, g_x2 + (size_t)row0 * IN_DIM + phase * 128 + ks * 16, IN_DIM);
#pragma unroll
            for (int nf = 0; nf < 8; nf++) {
                wmma::fragment<wmma::matrix_b, 16, 16, 16, __half, wmma::row_major> b;
                wmma::load_matrix_sync(b, &Ws[ks * 16][nf * 16], 128);
                wmma::mma_sync(accf[nf], a, b, accf[nf]);
            }
        }
        __syncthreads();
    }

    float* Hs = reinterpret_cast<float*>(&Ws[0][0]);
#pragma unroll
    for (int nf = 0; nf < 8; nf++)
        wmma::store_matrix_sync(Hs + (size_t)(warp * 16) * 128 + nf * 16,
                                accf[nf], 128, wmma::mem_row_major);
    __syncthreads();

    for (int v = threadIdx.x; v < 64 * 128 / 8; v += 128) {
        int base = v * 8;
        const float* p = Hs + base;
        __half2 a0 = __floats2half2_rn(p[0], p[1]);
        __half2 a1 = __floats2half2_rn(p[2], p[3]);
        __half2 a2 = __floats2half2_rn(p[4], p[5]);
        __half2 a3 = __floats2half2_rn(p[6], p[7]);
        uint4 pk;
        pk.x = *(uint32_t*)&a0; pk.y = *(uint32_t*)&a1;
        pk.z = *(uint32_t*)&a2; pk.w = *(uint32_t*)&a3;
        int grow = blockIdx.x * 64 + base / 128;
        int gcol = base % 128;
        *(uint4*)&g_h2[(size_t)grow * OUT_DIM + gcol] = pk;
    }
}

// ---------------------------------------------------------------------------
// Fused CSR gather (fp16 h) + spiking scan.
// One warp per dst node; HALF-warp per edge (16 lanes x 16B = 256B row).
// ---------------------------------------------------------------------------
__global__ __launch_bounds__(256) void k_gather_scan(float4* __restrict__ out) {
    int node = (blockIdx.x * 256 + threadIdx.x) >> 5;
    int lane = threadIdx.x & 31;
    if (node >= N_NODES) return;

    const int l16 = lane & 15;
    const int sel = lane >> 4;

    float di = g_dinv[node];
    float acc[8];
#pragma unroll
    for (int k = 0; k < 8; k++) acc[k] = 0.0f;

    if (sel == 0) {
        uint4 v = *(const uint4*)&g_h2[(size_t)node * OUT_DIM + l16 * 8];
        const __half2* hp = (const __half2*)&v;
        float di2 = di * di;
#pragma unroll
        for (int q = 0; q < 4; q++) {
            float2 f = __half22float2(hp[q]);
            acc[2 * q + 0] = f.x * di2;
            acc[2 * q + 1] = f.y * di2;
        }
    }

    int beg = g_off[node];
    int end = g_off[node + 1];

    for (int base = beg; base < end; base += 32) {
        int cnt = end - base;
        if (cnt > 32) cnt = 32;

        int   myidx = 0;
        float mynrm = 0.0f;
        if (lane < cnt) {
            myidx = g_srcs[base + lane];
            mynrm = g_dinv[myidx] * di;
        }

        int j = 0;
        for (; j + 8 <= cnt; j += 8) {
#pragma unroll
            for (int p = 0; p < 4; p++) {
                int   s  = __shfl_sync(0xffffffffu, myidx, j + 2 * p + sel);
                float nr = __shfl_sync(0xffffffffu, mynrm, j + 2 * p + sel);
                uint4 v = *(const uint4*)&g_h2[(size_t)s * OUT_DIM + l16 * 8];
                const __half2* hp = (const __half2*)&v;
#pragma unroll
                for (int q = 0; q < 4; q++) {
                    float2 f = __half22float2(hp[q]);
                    acc[2 * q + 0] += f.x * nr;
                    acc[2 * q + 1] += f.y * nr;
                }
            }
        }
        for (; j + 2 <= cnt; j += 2) {
            int   s  = __shfl_sync(0xffffffffu, myidx, j + sel);
            float nr = __shfl_sync(0xffffffffu, mynrm, j + sel);
            uint4 v = *(const uint4*)&g_h2[(size_t)s * OUT_DIM + l16 * 8];
            const __half2* hp = (const __half2*)&v;
#pragma unroll
            for (int q = 0; q < 4; q++) {
                float2 f = __half22float2(hp[q]);
                acc[2 * q + 0] += f.x * nr;
                acc[2 * q + 1] += f.y * nr;
            }
        }
        if (j < cnt) {
            int   s  = __shfl_sync(0xffffffffu, myidx, j);
            float nr = __shfl_sync(0xffffffffu, mynrm, j);
            if (sel == 0) {
                uint4 v = *(const uint4*)&g_h2[(size_t)s * OUT_DIM + l16 * 8];
                const __half2* hp = (const __half2*)&v;
#pragma unroll
                for (int q = 0; q < 4; q++) {
                    float2 f = __half22float2(hp[q]);
                    acc[2 * q + 0] += f.x * nr;
                    acc[2 * q + 1] += f.y * nr;
                }
            }
        }
    }

#pragma unroll
    for (int k = 0; k < 8; k++)
        acc[k] += __shfl_xor_sync(0xffffffffu, acc[k], 16);

    const int VEC = N_NODES * OUT_DIM / 4;
    int i = node * 32 + l16 * 2 + sel;
    int b = 4 * sel;
    float4 u = make_float4(acc[b + 0] * 0.1f, acc[b + 1] * 0.1f,
                           acc[b + 2] * 0.1f, acc[b + 3] * 0.1f);
    float4 z = make_float4(0.f, 0.f, 0.f, 0.f);

#pragma unroll
    for (int t = 0; t < T_STEPS; t++) {
        float4 Hm = make_float4(z.x + (u.x - z.x) * 0.5f,
                                z.y + (u.y - z.y) * 0.5f,
                                z.z + (u.z - z.z) * 0.5f,
                                z.w + (u.w - z.w) * 0.5f);
        float4 o = make_float4(Hm.x >= 1.0f ? 1.f : 0.f,
                               Hm.y >= 1.0f ? 1.f : 0.f,
                               Hm.z >= 1.0f ? 1.f : 0.f,
                               Hm.w >= 1.0f ? 1.f : 0.f);
        z = make_float4(Hm.x - o.x, Hm.y - o.y, Hm.z - o.z, Hm.w - o.w);
        __stcs(&out[(size_t)t * VEC + i], o);
        __stcs(&out[(size_t)(T_STEPS + t) * VEC + i], z);
    }
}

// ---------------------------------------------------------------------------
static cudaStream_t s_side = nullptr;
static cudaEvent_t  s_ev_fork = nullptr, s_ev_join = nullptr;

extern "C" void kernel_launch(void* const* d_in, const int* in_sizes, int n_in,
                              void* d_out, int out_size) {
    const float* x = (const float*)d_in[0];
    const float* W = (const float*)d_in[1];
    const int* ei = (const int*)d_in[2];
    float4* out = (float4*)d_out;

    if (s_side == nullptr) {
        cudaStreamCreateWithFlags(&s_side, cudaStreamNonBlocking);
        cudaEventCreateWithFlags(&s_ev_fork, cudaEventDisableTiming);
        cudaEventCreateWithFlags(&s_ev_join, cudaEventDisableTiming);
    }

    cudaEventRecord(s_ev_fork, 0);
    cudaStreamWaitEvent(s_side, s_ev_fork, 0);

    // side stream: CSR build chain (ILP-batched)
    k_zero_cnt<<<(N_NODES / 4 + 255) / 256, 256, 0, s_side>>>();
    k_hist<<<(N_EDGES / 8 + 255) / 256, 256, 0, s_side>>>(ei);
    k_offsets<<<1, 1024, 0, s_side>>>();
    k_csr<<<(N_EDGES / 4 + 255) / 256, 256, 0, s_side>>>(ei);
    cudaEventRecord(s_ev_join, s_side);

    // main stream: fp16 convert + tensor-core GEMM
    k_cvt_x<<<(N_PAD * IN_DIM / 4 + 255) / 256, 256>>>(x);
    k_gemm_hmma<<<N_PAD / 64, 128>>>(W);

    cudaStreamWaitEvent(0, s_ev_join, 0);
    k_gather_scan<<<(N_NODES * 32 + 255) / 256, 256>>>(out);
}

// round 10
// speedup vs baseline: 1.1768x; 1.1768x over previous
#include <cuda_runtime.h>
#include <cuda_fp16.h>
#include <mma.h>
#include <cstdint>

using namespace nvcuda;

#define N_NODES 50000
#define N_PAD   50048   // 782 * 64
#define N_EDGES 1600000
#define IN_DIM  256
#define OUT_DIM 128
#define T_STEPS 8
#define BUCKET  96
#define OVF_CAP 32768

// Scratch (device globals — no allocation allowed)
__device__ __align__(16) __half g_x2[N_PAD * IN_DIM];    // x in fp16 (padded)
__device__ __align__(16) __half g_h2[N_PAD * OUT_DIM];   // h = x @ W (fp16)
__device__ float g_dinv[N_NODES];
__device__ __align__(16) int g_cnt[N_NODES];
__device__ int   g_srcs[N_NODES * BUCKET];   // bucketed adjacency (by dst)
__device__ int   g_ovf_cnt;
__device__ int2  g_ovf[OVF_CAP];             // (dst, src) overflow pairs

// ---------------------------------------------------------------------------
__global__ void k_zero_cnt() {
    int i = blockIdx.x * blockDim.x + threadIdx.x;
    if (i < N_NODES / 4) ((int4*)g_cnt)[i] = make_int4(0, 0, 0, 0);
    if (i == 0) g_ovf_cnt = 0;
}

// One-pass bucketed CSR build: count + place src in dst's bucket.
__global__ __launch_bounds__(256) void k_bucket(const int* __restrict__ ei) {
    int t = blockIdx.x * blockDim.x + threadIdx.x;
    if (t >= N_EDGES / 4) return;
    int4 s = ((const int4*)ei)[t];
    int4 d = ((const int4*)(ei + N_EDGES))[t];
#pragma unroll
    for (int k = 0; k < 4; k++) {
        int dst = (k == 0) ? d.x : (k == 1) ? d.y : (k == 2) ? d.z : d.w;
        int src = (k == 0) ? s.x : (k == 1) ? s.y : (k == 2) ? s.z : s.w;
        int pos = atomicAdd(&g_cnt[dst], 1);
        if (pos < BUCKET) {
            g_srcs[dst * BUCKET + pos] = src;
        } else {
            int o = atomicAdd(&g_ovf_cnt, 1);
            if (o < OVF_CAP) g_ovf[o] = make_int2(dst, src);
        }
    }
}

__global__ void k_dinv() {
    int n = blockIdx.x * blockDim.x + threadIdx.x;
    if (n < N_NODES) g_dinv[n] = rsqrtf((float)(g_cnt[n] + 1));
}

// ---------------------------------------------------------------------------
// x fp32 -> fp16 (padded rows zero-filled)
// ---------------------------------------------------------------------------
__global__ __launch_bounds__(256) void k_cvt_x(const float* __restrict__ x) {
    const int TOT = N_PAD * IN_DIM / 4;
    int i = blockIdx.x * blockDim.x + threadIdx.x;
    if (i >= TOT) return;
    int row = i / (IN_DIM / 4);
    uint2 pk;
    if (row < N_NODES) {
        float4 v = ((const float4*)x)[i];
        __half2 h0 = __floats2half2_rn(v.x, v.y);
        __half2 h1 = __floats2half2_rn(v.z, v.w);
        pk.x = *(uint32_t*)&h0;
        pk.y = *(uint32_t*)&h1;
    } else {
        pk = make_uint2(0u, 0u);
    }
    ((uint2*)g_x2)[i] = pk;
}

// ---------------------------------------------------------------------------
// HMMA GEMM: h = x @ W via wmma 16x16x16 fp16 x fp16 + fp32 acc.
// ---------------------------------------------------------------------------
__global__ __launch_bounds__(128) void k_gemm_hmma(const float* __restrict__ W) {
    __shared__ __half Ws[128][128];   // 32 KB; aliased as fp32 staging on exit

    const int warp = threadIdx.x >> 5;
    const int row0 = blockIdx.x * 64 + warp * 16;

    wmma::fragment<wmma::accumulator, 16, 16, 16, float> accf[8];
#pragma unroll
    for (int nf = 0; nf < 8; nf++) wmma::fill_fragment(accf[nf], 0.0f);

#pragma unroll
    for (int phase = 0; phase < 2; phase++) {
        for (int idx = threadIdx.x; idx < 128 * 128 / 4; idx += 128) {
            int r = idx / 32;
            int c4 = idx % 32;
            float4 v = *(const float4*)&W[(size_t)(phase * 128 + r) * OUT_DIM + c4 * 4];
            __half2 h0 = __floats2half2_rn(v.x, v.y);
            __half2 h1 = __floats2half2_rn(v.z, v.w);
            uint2 pk;
            pk.x = *(uint32_t*)&h0;
            pk.y = *(uint32_t*)&h1;
            *(uint2*)&Ws[r][c4 * 4] = pk;
        }
        __syncthreads();

#pragma unroll
        for (int ks = 0; ks < 8; ks++) {
            wmma::fragment<wmma::matrix_a, 16, 16, 16, __half, wmma::row_major> a;
            wmma::load_matrix_sync(a, g_x2 + (size_t)row0 * IN_DIM + phase * 128 + ks * 16, IN_DIM);
#pragma unroll
            for (int nf = 0; nf < 8; nf++) {
                wmma::fragment<wmma::matrix_b, 16, 16, 16, __half, wmma::row_major> b;
                wmma::load_matrix_sync(b, &Ws[ks * 16][nf * 16], 128);
                wmma::mma_sync(accf[nf], a, b, accf[nf]);
            }
        }
        __syncthreads();
    }

    float* Hs = reinterpret_cast<float*>(&Ws[0][0]);
#pragma unroll
    for (int nf = 0; nf < 8; nf++)
        wmma::store_matrix_sync(Hs + (size_t)(warp * 16) * 128 + nf * 16,
                                accf[nf], 128, wmma::mem_row_major);
    __syncthreads();

    for (int v = threadIdx.x; v < 64 * 128 / 8; v += 128) {
        int base = v * 8;
        const float* p = Hs + base;
        __half2 a0 = __floats2half2_rn(p[0], p[1]);
        __half2 a1 = __floats2half2_rn(p[2], p[3]);
        __half2 a2 = __floats2half2_rn(p[4], p[5]);
        __half2 a3 = __floats2half2_rn(p[6], p[7]);
        uint4 pk;
        pk.x = *(uint32_t*)&a0; pk.y = *(uint32_t*)&a1;
        pk.z = *(uint32_t*)&a2; pk.w = *(uint32_t*)&a3;
        int grow = blockIdx.x * 64 + base / 128;
        int gcol = base % 128;
        *(uint4*)&g_h2[(size_t)grow * OUT_DIM + gcol] = pk;
    }
}

// ---------------------------------------------------------------------------
// Fused bucket gather (fp16 h) + spiking scan.
// One warp per dst node; HALF-warp per edge (16 lanes x 16B = 256B row).
// ---------------------------------------------------------------------------
__global__ __launch_bounds__(256) void k_gather_scan(float4* __restrict__ out) {
    int node = (blockIdx.x * 256 + threadIdx.x) >> 5;
    int lane = threadIdx.x & 31;
    if (node >= N_NODES) return;

    const int l16 = lane & 15;
    const int sel = lane >> 4;

    float di = g_dinv[node];
    float acc[8];
#pragma unroll
    for (int k = 0; k < 8; k++) acc[k] = 0.0f;

    if (sel == 0) {
        uint4 v = *(const uint4*)&g_h2[(size_t)node * OUT_DIM + l16 * 8];
        const __half2* hp = (const __half2*)&v;
        float di2 = di * di;
#pragma unroll
        for (int q = 0; q < 4; q++) {
            float2 f = __half22float2(hp[q]);
            acc[2 * q + 0] = f.x * di2;
            acc[2 * q + 1] = f.y * di2;
        }
    }

    int deg = g_cnt[node];
    int cnt_b = deg < BUCKET ? deg : BUCKET;
    int beg = node * BUCKET;
    int end = beg + cnt_b;

    for (int base = beg; base < end; base += 32) {
        int cnt = end - base;
        if (cnt > 32) cnt = 32;

        int   myidx = 0;
        float mynrm = 0.0f;
        if (lane < cnt) {
            myidx = g_srcs[base + lane];
            mynrm = g_dinv[myidx] * di;
        }

        int j = 0;
        for (; j + 8 <= cnt; j += 8) {
#pragma unroll
            for (int p = 0; p < 4; p++) {
                int   s  = __shfl_sync(0xffffffffu, myidx, j + 2 * p + sel);
                float nr = __shfl_sync(0xffffffffu, mynrm, j + 2 * p + sel);
                uint4 v = *(const uint4*)&g_h2[(size_t)s * OUT_DIM + l16 * 8];
                const __half2* hp = (const __half2*)&v;
#pragma unroll
                for (int q = 0; q < 4; q++) {
                    float2 f = __half22float2(hp[q]);
                    acc[2 * q + 0] += f.x * nr;
                    acc[2 * q + 1] += f.y * nr;
                }
            }
        }
        for (; j + 2 <= cnt; j += 2) {
            int   s  = __shfl_sync(0xffffffffu, myidx, j + sel);
            float nr = __shfl_sync(0xffffffffu, mynrm, j + sel);
            uint4 v = *(const uint4*)&g_h2[(size_t)s * OUT_DIM + l16 * 8];
            const __half2* hp = (const __half2*)&v;
#pragma unroll
            for (int q = 0; q < 4; q++) {
                float2 f = __half22float2(hp[q]);
                acc[2 * q + 0] += f.x * nr;
                acc[2 * q + 1] += f.y * nr;
            }
        }
        if (j < cnt) {
            int   s  = __shfl_sync(0xffffffffu, myidx, j);
            float nr = __shfl_sync(0xffffffffu, mynrm, j);
            if (sel == 0) {
                uint4 v = *(const uint4*)&g_h2[(size_t)s * OUT_DIM + l16 * 8];
                const __half2* hp = (const __half2*)&v;
#pragma unroll
                for (int q = 0; q < 4; q++) {
                    float2 f = __half22float2(hp[q]);
                    acc[2 * q + 0] += f.x * nr;
                    acc[2 * q + 1] += f.y * nr;
                }
            }
        }
    }

    // overflow edges (deg > BUCKET): astronomically rare, handled for correctness
    if (deg > BUCKET) {
        int novf = g_ovf_cnt;
        if (novf > OVF_CAP) novf = OVF_CAP;
        for (int k = 0; k < novf; k++) {
            int2 p = g_ovf[k];
            if (p.x == node && sel == 0) {
                float nr = g_dinv[p.y] * di;
                uint4 v = *(const uint4*)&g_h2[(size_t)p.y * OUT_DIM + l16 * 8];
                const __half2* hp = (const __half2*)&v;
#pragma unroll
                for (int q = 0; q < 4; q++) {
                    float2 f = __half22float2(hp[q]);
                    acc[2 * q + 0] += f.x * nr;
                    acc[2 * q + 1] += f.y * nr;
                }
            }
        }
    }

#pragma unroll
    for (int k = 0; k < 8; k++)
        acc[k] += __shfl_xor_sync(0xffffffffu, acc[k], 16);

    const int VEC = N_NODES * OUT_DIM / 4;
    int i = node * 32 + l16 * 2 + sel;
    int b = 4 * sel;
    float4 u = make_float4(acc[b + 0] * 0.1f, acc[b + 1] * 0.1f,
                           acc[b + 2] * 0.1f, acc[b + 3] * 0.1f);
    float4 z = make_float4(0.f, 0.f, 0.f, 0.f);

#pragma unroll
    for (int t = 0; t < T_STEPS; t++) {
        float4 Hm = make_float4(z.x + (u.x - z.x) * 0.5f,
                                z.y + (u.y - z.y) * 0.5f,
                                z.z + (u.z - z.z) * 0.5f,
                                z.w + (u.w - z.w) * 0.5f);
        float4 o = make_float4(Hm.x >= 1.0f ? 1.f : 0.f,
                               Hm.y >= 1.0f ? 1.f : 0.f,
                               Hm.z >= 1.0f ? 1.f : 0.f,
                               Hm.w >= 1.0f ? 1.f : 0.f);
        z = make_float4(Hm.x - o.x, Hm.y - o.y, Hm.z - o.z, Hm.w - o.w);
        __stcs(&out[(size_t)t * VEC + i], o);
        __stcs(&out[(size_t)(T_STEPS + t) * VEC + i], z);
    }
}

// ---------------------------------------------------------------------------
static cudaStream_t s_side = nullptr;
static cudaEvent_t  s_ev_fork = nullptr, s_ev_join = nullptr;

extern "C" void kernel_launch(void* const* d_in, const int* in_sizes, int n_in,
                              void* d_out, int out_size) {
    const float* x = (const float*)d_in[0];
    const float* W = (const float*)d_in[1];
    const int* ei = (const int*)d_in[2];
    float4* out = (float4*)d_out;

    if (s_side == nullptr) {
        cudaStreamCreateWithFlags(&s_side, cudaStreamNonBlocking);
        cudaEventCreateWithFlags(&s_ev_fork, cudaEventDisableTiming);
        cudaEventCreateWithFlags(&s_ev_join, cudaEventDisableTiming);
    }

    cudaEventRecord(s_ev_fork, 0);
    cudaStreamWaitEvent(s_side, s_ev_fork, 0);

    // side stream: one-pass bucketed CSR + dinv
    k_zero_cnt<<<(N_NODES / 4 + 255) / 256, 256, 0, s_side>>>();
    k_bucket<<<(N_EDGES / 4 + 255) / 256, 256, 0, s_side>>>(ei);
    k_dinv<<<(N_NODES + 255) / 256, 256, 0, s_side>>>();
    cudaEventRecord(s_ev_join, s_side);

    // main stream: fp16 convert + tensor-core GEMM
    k_cvt_x<<<(N_PAD * IN_DIM / 4 + 255) / 256, 256>>>(x);
    k_gemm_hmma<<<N_PAD / 64, 128>>>(W);

    cudaStreamWaitEvent(0, s_ev_join, 0);
    k_gather_scan<<<(N_NODES * 32 + 255) / 256, 256>>>(out);
}